// round 3
// baseline (speedup 1.0000x reference)
#include <cuda_runtime.h>

// out[b, 0, h, w] = 0.5f * (x[b,0,h,w] + x[b,1,h,w] + x[b,2,h,w])
// Exact algebraic collapse of the diagonal Haar decompose + reconstruct
// (see R0 derivation: every output pixel = 0.5 * channel-sum at same (h,w)).
//
// R3: keep MLP=6 (2 float4 per thread x 3 channels) but stride the per-thread
// pair by blockDim so every warp LDG.128 is a contiguous 512B access
// (R2's adjacent-pair layout half-filled sectors and doubled L1 wavefronts).
// Plain loads (no reuse to protect), streaming stores.

static constexpr int B = 16;
static constexpr int C = 3;
static constexpr long long HW = 1024LL * 1024LL;            // elems per plane (2^20)
static constexpr long long OUT_ELEMS = (long long)B * HW;   // 16,777,216
static constexpr long long OUT_VECS = OUT_ELEMS / 4;        // 4,194,304 float4s
static constexpr int THREADS = 512;
static constexpr int VPT = 2;                               // float4s per thread
// vecs per block = THREADS * VPT = 1024; grid = 4096 blocks, exact cover.
static constexpr long long VECS_PER_BLOCK = (long long)THREADS * VPT;
static constexpr int GRID = (int)(OUT_VECS / VECS_PER_BLOCK);   // 4096

__global__ void __launch_bounds__(THREADS) haar_chansum_kernel(
    const float* __restrict__ x, float* __restrict__ out) {
    // Block's first vec; thread handles vecs v0 and v0 + THREADS (both within
    // the block's 1024-vec = 4096-element chunk, which never crosses a plane
    // boundary since HW/4 = 262144 is a multiple of 1024).
    long long v0 = (long long)blockIdx.x * VECS_PER_BLOCK + threadIdx.x;
    long long e0 = v0 * 4;                  // element index of first float4
    long long b  = e0 >> 20;                // batch (HW = 2^20)
    long long p  = e0 & (HW - 1);           // pixel within plane
    const float* base = x + (b * C) * HW + p;

    const long long S = (long long)THREADS * 4;   // element stride to 2nd vec (2048)

    const float4* c0 = reinterpret_cast<const float4*>(base);
    const float4* c1 = reinterpret_cast<const float4*>(base + HW);
    const float4* c2 = reinterpret_cast<const float4*>(base + 2LL * HW);

    // 6 independent, fully-coalesced LDG.128 (each warp access = 512B contiguous)
    float4 a0 = c0[0];
    float4 a1 = c1[0];
    float4 a2 = c2[0];
    float4 b0 = c0[THREADS];
    float4 b1 = c1[THREADS];
    float4 b2 = c2[THREADS];

    float4 r0, r1;
    r0.x = 0.5f * (a0.x + a1.x + a2.x);
    r0.y = 0.5f * (a0.y + a1.y + a2.y);
    r0.z = 0.5f * (a0.z + a1.z + a2.z);
    r0.w = 0.5f * (a0.w + a1.w + a2.w);
    r1.x = 0.5f * (b0.x + b1.x + b2.x);
    r1.y = 0.5f * (b0.y + b1.y + b2.y);
    r1.z = 0.5f * (b0.z + b1.z + b2.z);
    r1.w = 0.5f * (b0.w + b1.w + b2.w);

    float4* o = reinterpret_cast<float4*>(out + e0);
    __stcs(o + 0, r0);
    __stcs(o + THREADS, r1);
    (void)S;
}

extern "C" void kernel_launch(void* const* d_in, const int* in_sizes, int n_in,
                              void* d_out, int out_size) {
    const float* x = (const float*)d_in[0];
    float* out = (float*)d_out;
    haar_chansum_kernel<<<GRID, THREADS>>>(x, out);
}